// round 8
// baseline (speedup 1.0000x reference)
#include <cuda_runtime.h>
#include <cstdint>
#include <math.h>

// Shape fixed by setup_inputs: B=2, H=16, S=2048, D=128, key block = 256
#define S_LEN 2048
#define D_DIM 128
#define BH 32
#define NT 512
#define FULLM 0xffffffffu

// smem layout (floats)
#define QSTR 132
#define Q_FLOATS (64 * QSTR)                       // 8448
#define SLOT_FLOATS (64 * 128)                     // 8192 (64 keys x 128 d, no pad)
#define NSLOT 5
#define SLOTS_OFF Q_FLOATS
#define PBUF_OFF (SLOTS_OFF + NSLOT * SLOT_FLOATS) // pmax[2][256], psum[2][256]
#define MBAR_OFF (PBUF_OFF + 1024)                 // 10 x u64 barriers
#define SMEM_FLOATS (MBAR_OFF + 64)
#define OSTR 132

// tf32-prerounded K/V scratch
__device__ float g_Kr[(size_t)BH * S_LEN * D_DIM];
__device__ float g_Vr[(size_t)BH * S_LEN * D_DIM];

__device__ __forceinline__ uint32_t tf32b(float x) {
    uint32_t u; asm("cvt.rna.tf32.f32 %0, %1;" : "=r"(u) : "f"(x)); return u;
}
__device__ __forceinline__ float tf32r(float x) { return __uint_as_float(tf32b(x)); }

__device__ __forceinline__ uint32_t smem_u32(const void* p) {
    uint32_t a;
    asm("{ .reg .u64 t; cvta.to.shared.u64 t, %1; cvt.u32.u64 %0, t; }" : "=r"(a) : "l"(p));
    return a;
}

#define MB_INIT(mb, c) asm volatile("mbarrier.init.shared.b64 [%0], %1;" :: "r"(mb), "r"(c) : "memory")
#define MB_ARRIVE(mb)  asm volatile("mbarrier.arrive.shared.b64 _, [%0];" :: "r"(mb) : "memory")
#define CP16(dst, src) asm volatile("cp.async.cg.shared.global [%0], [%1], 16;" :: "r"(dst), "l"(src) : "memory")
// .noinc is load-bearing (R6 hang without it).
#define CP_ARRIVE(mb)  asm volatile("cp.async.mbarrier.arrive.noinc.shared.b64 [%0];" :: "r"(mb) : "memory")
// named barrier: only the 4 warps of one m-group participate (128 threads)
#define BAR_SYNC(id)   asm volatile("bar.sync %0, 128;" :: "r"(id) : "memory")

#define MB_WAIT(mbar_addr, phase) do {                                             \
    uint32_t _mb = (mbar_addr); uint32_t _ph = (phase); uint32_t _done;            \
    asm volatile("{ .reg .pred p; mbarrier.try_wait.parity.acquire.cta.shared::cta.b64 p, [%1], %2; selp.b32 %0, 1, 0, p; }" \
        : "=r"(_done) : "r"(_mb), "r"(_ph) : "memory");                            \
    if (!_done) {                                                                  \
        asm volatile("{ .reg .pred P1; WL_%=: mbarrier.try_wait.parity.acquire.cta.shared::cta.b64 P1, [%0], %1, 0x989680; @P1 bra.uni WD_%=; bra.uni WL_%=; WD_%=: }" \
            :: "r"(_mb), "r"(_ph) : "memory");                                     \
    }                                                                              \
} while (0)

// m16n8k8 tf32 HMMA, D += A*B
__device__ __forceinline__ void mma8(float* c, uint32_t a0, uint32_t a1,
                                     uint32_t a2, uint32_t a3,
                                     uint32_t b0, uint32_t b1) {
    asm volatile(
        "mma.sync.aligned.m16n8k8.row.col.f32.tf32.tf32.f32 "
        "{%0,%1,%2,%3}, {%4,%5,%6,%7}, {%8,%9}, {%0,%1,%2,%3};"
        : "+f"(c[0]), "+f"(c[1]), "+f"(c[2]), "+f"(c[3])
        : "r"(a0), "r"(a1), "r"(a2), "r"(a3), "r"(b0), "r"(b1));
}

// ---------------------------------------------------------------------------
// Pre-pass: round K, V to tf32 (rna) into scratch.
// ---------------------------------------------------------------------------
__global__ void round_kernel(const float* __restrict__ K, const float* __restrict__ V) {
    size_t i = (size_t)blockIdx.x * 256 + threadIdx.x;
    const float4* s = (const float4*)(blockIdx.y ? V : K);
    float4* d = (float4*)(blockIdx.y ? g_Vr : g_Kr);
    float4 v = s[i];
    v.x = tf32r(v.x); v.y = tf32r(v.y); v.z = tf32r(v.z); v.w = tf32r(v.w);
    d[i] = v;
}

// ---------------------------------------------------------------------------
// Main kernel. CTA: 64 q rows, 16 warps = 4(m) x 4(kg: 64 keys).
// Chunk ring (5 slots, mbarrier full/empty), XOR-swizzled, cp.async staged.
// Softmax merge synced per m-group via named barriers (not CTA-wide).
// ---------------------------------------------------------------------------
__global__ __launch_bounds__(NT, 1)
void attn_mma_kernel(const float* __restrict__ Q, float* __restrict__ O) {
    extern __shared__ float smf[];
    const uint32_t sbase = smem_u32(smf);
    const uint32_t slots_sa = sbase + SLOTS_OFF * 4;
    const uint32_t mb_full  = sbase + MBAR_OFF * 4;        // 5 x u64
    const uint32_t mb_empty = mb_full + NSLOT * 8;         // 5 x u64
    float* qs = smf;
    float* pmax = smf + PBUF_OFF;                          // [2][256]
    float* psum = pmax + 512;

    const int tid  = threadIdx.x;
    const int wid  = tid >> 5;
    const int lane = tid & 31;
    const int m  = wid & 3;
    const int kg = wid >> 2;
    const int g = lane >> 2;
    const int t = lane & 3;
    const int g3 = g & 3;
    const int g24 = (g >> 2) << 2;     // 4*(g>>2)

    const int bh = blockIdx.y;
    const int qb = blockIdx.x;
    const size_t bhoff = (size_t)bh * S_LEN * D_DIM;
    const float* Qb = Q + bhoff + (size_t)qb * 64 * D_DIM;
    const float* Krb = g_Kr + bhoff;
    const float* Vrb = g_Vr + bhoff;
    float* Ob = O + bhoff + (size_t)qb * 64 * D_DIM;

    // ---- init barriers ----
    if (tid == 0) {
        #pragma unroll
        for (int s = 0; s < NSLOT; s++) {
            MB_INIT(mb_full + s * 8, NT);     // one cp-arrive per thread
            MB_INIT(mb_empty + s * 8, 128);   // 4 consumer warps
        }
    }
    __syncthreads();

    // ---- producer lambda: stage chunk n (if n < 64) ----
    auto produce = [&](int n) {
        if (n >= 64) return;
        int q5 = n / 5;
        int slot = n - q5 * 5;
        uint32_t db = slots_sa + (uint32_t)slot * (SLOT_FLOATS * 4);
        if (n >= 5) MB_WAIT(mb_empty + slot * 8, (q5 - 1) & 1);
        int r = n & 7;
        const float* src = ((r < 4) ? Krb : Vrb)
                         + ((size_t)((n >> 3) * 256 + (r & 3) * 64)) * D_DIM;
        #pragma unroll
        for (int i = 0; i < 4; i++) {
            int u = tid + NT * i;           // 0..2047
            int row = u >> 5;               // 0..63
            int c16 = u & 31;
            int r3 = row & 7;
            int f = ((r3 & 3) << 1) | (r3 >> 2);
            uint32_t dst = db + (uint32_t)row * 512 + (uint32_t)((c16 ^ f) << 4);
            CP16(dst, src + row * D_DIM + c16 * 4);
        }
        CP_ARRIVE(mb_full + slot * 8);
    };

    // ---- stage Q (tf32, stride 132) ----
    #pragma unroll
    for (int i = 0; i < 2048 / NT; i++) {
        int idx = tid + NT * i;
        int r = idx >> 5;
        int c4 = (idx & 31) << 2;
        float4 v = *(const float4*)(Qb + (size_t)r * D_DIM + c4);
        v.x = tf32r(v.x); v.y = tf32r(v.y); v.z = tf32r(v.z); v.w = tf32r(v.w);
        *(float4*)(qs + r * QSTR + c4) = v;
    }

    // prologue: fill the ring
    produce(0); produce(1); produce(2); produce(3); produce(4);

    float oacc[16][4];
    #pragma unroll
    for (int dt = 0; dt < 16; dt++)
        #pragma unroll
        for (int j = 0; j < 4; j++) oacc[dt][j] = 0.0f;

    const float cexp = 0.08838834764831845f * 1.4426950408889634f; // D^-0.5*log2(e)
    const int srcA = (lane & ~3) | (t >> 1);
    const int srcB = srcA + 2;
    const bool odd = (t & 1) != 0;
    const int row0 = 16 * m + g;
    const float* a0p = qs + row0 * QSTR + t;
    const float* a1p = a0p + 8 * QSTR;

    __syncthreads();   // Q visible + barrier init

    #pragma unroll 1
    for (int jb = 0; jb < 8; jb++) {
        const int base = jb * 8;

        // ================= QK consume: chunk base+kg =========================
        const int nk = base + kg;
        const int qk5 = nk / 5, sk = nk - qk5 * 5;
        MB_WAIT(mb_full + sk * 8, qk5 & 1);
        const float* kb = smf + SLOTS_OFF + sk * SLOT_FLOATS;

        float c[8][4];
        #pragma unroll
        for (int nt = 0; nt < 8; nt++)
            #pragma unroll
            for (int j = 0; j < 4; j++) c[nt][j] = 0.0f;

        // A-fragment prefetch pipeline (distance 1)
        {
            uint32_t A0 = __float_as_uint(a0p[0]);
            uint32_t A1 = __float_as_uint(a1p[0]);
            uint32_t A2 = __float_as_uint(a0p[4]);
            uint32_t A3 = __float_as_uint(a1p[4]);
            #pragma unroll 4
            for (int ks = 0; ks < 16; ks++) {
                uint32_t N0 = 0, N1 = 0, N2 = 0, N3 = 0;
                if (ks < 15) {
                    N0 = __float_as_uint(a0p[(ks + 1) * 8]);
                    N1 = __float_as_uint(a1p[(ks + 1) * 8]);
                    N2 = __float_as_uint(a0p[(ks + 1) * 8 + 4]);
                    N3 = __float_as_uint(a1p[(ks + 1) * 8 + 4]);
                }
                const int off0 = ((ks ^ g3) << 3) + g24 + t;
                const int off1 = off0 ^ 4;
                #pragma unroll
                for (int nt = 0; nt < 8; nt++) {
                    const float* kp = kb + (nt * 8 + g) * 128;
                    mma8(c[nt], A0, A1, A2, A3,
                         __float_as_uint(kp[off0]), __float_as_uint(kp[off1]));
                }
                A0 = N0; A1 = N1; A2 = N2; A3 = N3;
            }
        }
        MB_ARRIVE(mb_empty + sk * 8);

        // overlap: stage this jb's V1..V3
        produce(base + 5); produce(base + 6); produce(base + 7);

        // ================= softmax (local 64 keys) ============================
        float m0 = -INFINITY, m1 = -INFINITY;
        #pragma unroll
        for (int nt = 0; nt < 8; nt++) {
            m0 = fmaxf(m0, fmaxf(c[nt][0], c[nt][1]));
            m1 = fmaxf(m1, fmaxf(c[nt][2], c[nt][3]));
        }
        m0 = fmaxf(m0, __shfl_xor_sync(FULLM, m0, 1));
        m0 = fmaxf(m0, __shfl_xor_sync(FULLM, m0, 2));
        m1 = fmaxf(m1, __shfl_xor_sync(FULLM, m1, 1));
        m1 = fmaxf(m1, __shfl_xor_sync(FULLM, m1, 2));

        float s0 = 0.0f, s1 = 0.0f;
        #pragma unroll
        for (int nt = 0; nt < 8; nt++) {
            c[nt][0] = exp2f((c[nt][0] - m0) * cexp); s0 += c[nt][0];
            c[nt][1] = exp2f((c[nt][1] - m0) * cexp); s0 += c[nt][1];
            c[nt][2] = exp2f((c[nt][2] - m1) * cexp); s1 += c[nt][2];
            c[nt][3] = exp2f((c[nt][3] - m1) * cexp); s1 += c[nt][3];
        }
        s0 += __shfl_xor_sync(FULLM, s0, 1);
        s0 += __shfl_xor_sync(FULLM, s0, 2);
        s1 += __shfl_xor_sync(FULLM, s1, 1);
        s1 += __shfl_xor_sync(FULLM, s1, 2);

        float* pmx = pmax + (jb & 1) * 256;
        float* psm = psum + (jb & 1) * 256;
        if (t == 0) {
            pmx[kg * 64 + row0] = m0;  pmx[kg * 64 + row0 + 8] = m1;
            psm[kg * 64 + row0] = s0;  psm[kg * 64 + row0 + 8] = s1;
        }
        // merge data is written/read only within this m-group's 4 warps:
        // a 128-thread named barrier replaces the CTA-wide sync.
        BAR_SYNC(1 + m);

        float scale0, scale1;
        {
            float M0 = -INFINITY, M1 = -INFINITY;
            #pragma unroll
            for (int j = 0; j < 4; j++) {
                M0 = fmaxf(M0, pmx[j * 64 + row0]);
                M1 = fmaxf(M1, pmx[j * 64 + row0 + 8]);
            }
            float S0 = 0.0f, S1 = 0.0f;
            #pragma unroll
            for (int j = 0; j < 4; j++) {
                S0 += psm[j * 64 + row0]     * exp2f((pmx[j * 64 + row0]     - M0) * cexp);
                S1 += psm[j * 64 + row0 + 8] * exp2f((pmx[j * 64 + row0 + 8] - M1) * cexp);
            }
            scale0 = exp2f((m0 - M0) * cexp) / S0;
            scale1 = exp2f((m1 - M1) * cexp) / S1;
        }

        // next-jb K0 can be staged now
        produce(base + 8);

        // ===== permute P: C-layout (2t,2t+1) -> A-layout (t,t+4), tf32 ========
        #pragma unroll
        for (int nt = 0; nt < 8; nt++) {
            float x0 = c[nt][0] * scale0, x1 = c[nt][1] * scale0;
            float x2 = c[nt][2] * scale1, x3 = c[nt][3] * scale1;
            float e0 = __shfl_sync(FULLM, x0, srcA), e1 = __shfl_sync(FULLM, x1, srcA);
            float f0 = __shfl_sync(FULLM, x0, srcB), f1 = __shfl_sync(FULLM, x1, srcB);
            float u0 = __shfl_sync(FULLM, x2, srcA), u1 = __shfl_sync(FULLM, x3, srcA);
            float v0 = __shfl_sync(FULLM, x2, srcB), v1 = __shfl_sync(FULLM, x3, srcB);
            c[nt][0] = tf32r(odd ? e1 : e0);
            c[nt][1] = tf32r(odd ? u1 : u0);
            c[nt][2] = tf32r(odd ? f1 : f0);
            c[nt][3] = tf32r(odd ? v1 : v0);
        }

        // ================= PV consume: chunk base+4+kg ========================
        const int nv = base + 4 + kg;
        const int qv5 = nv / 5, sv = nv - qv5 * 5;
        MB_WAIT(mb_full + sv * 8, qv5 & 1);
        const float* vb = smf + SLOTS_OFF + sv * SLOT_FLOATS;

        #pragma unroll 2
        for (int kc = 0; kc < 8; kc++) {
            const float* vr = vb + (kc * 8 + t) * 128;
            uint32_t A0 = __float_as_uint(c[kc][0]);
            uint32_t A1 = __float_as_uint(c[kc][1]);
            uint32_t A2 = __float_as_uint(c[kc][2]);
            uint32_t A3 = __float_as_uint(c[kc][3]);
            // B-fragment prefetch pipeline (distance 1)
            uint32_t B0 = __float_as_uint(vr[((0 ^ t) << 3) + g24 + g3]);
            uint32_t B1 = __float_as_uint(vr[((((0 ^ t) << 3) + g24 + g3) ^ 4) + 512]);
            #pragma unroll
            for (int dt = 0; dt < 16; dt++) {
                uint32_t Nb0 = 0, Nb1 = 0;
                if (dt < 15) {
                    const int no0 = (((dt + 1) ^ t) << 3) + g24 + g3;
                    Nb0 = __float_as_uint(vr[no0]);
                    Nb1 = __float_as_uint(vr[(no0 ^ 4) + 512]);
                }
                mma8(oacc[dt], A0, A1, A2, A3, B0, B1);
                B0 = Nb0; B1 = Nb1;
            }
        }
        MB_ARRIVE(mb_empty + sv * 8);

        // stage remaining next-jb chunks: K1..K3, V0'
        produce(base + 9); produce(base + 10); produce(base + 11); produce(base + 12);
    }

    // ================= combine 4 kg partials, write O =========================
    __syncthreads();   // all consumption done; safe to reuse smem
    float* obuf = smf;
    if (kg != 0) {
        float* p0 = obuf + ((kg - 1) * 64 + row0) * OSTR + 2 * t;
        float* p1 = p0 + 8 * OSTR;
        #pragma unroll
        for (int dt = 0; dt < 16; dt++) {
            *(float2*)(p0 + dt * 8) = make_float2(oacc[dt][0], oacc[dt][1]);
            *(float2*)(p1 + dt * 8) = make_float2(oacc[dt][2], oacc[dt][3]);
        }
    }
    __syncthreads();
    if (kg == 0) {
        float* o0 = Ob + (size_t)row0 * D_DIM + 2 * t;
        float* o1 = o0 + 8 * D_DIM;
        const float* p0 = obuf + row0 * OSTR + 2 * t;
        const float* p1 = p0 + 8 * OSTR;
        #pragma unroll
        for (int dt = 0; dt < 16; dt++) {
            float a0 = oacc[dt][0], a1 = oacc[dt][1];
            float a2 = oacc[dt][2], a3 = oacc[dt][3];
            #pragma unroll
            for (int j = 0; j < 3; j++) {
                float2 q0 = *(const float2*)(p0 + j * 64 * OSTR + dt * 8);
                float2 q1 = *(const float2*)(p1 + j * 64 * OSTR + dt * 8);
                a0 += q0.x; a1 += q0.y; a2 += q1.x; a3 += q1.y;
            }
            *(float2*)(o0 + dt * 8) = make_float2(a0, a1);
            *(float2*)(o1 + dt * 8) = make_float2(a2, a3);
        }
    }
}

// ---------------------------------------------------------------------------
extern "C" void kernel_launch(void* const* d_in, const int* in_sizes, int n_in,
                              void* d_out, int out_size) {
    const float* Q = (const float*)d_in[0];
    const float* K = (const float*)d_in[1];
    const float* V = (const float*)d_in[2];
    float* O = (float*)d_out;

    const int bh = in_sizes[0] / (S_LEN * D_DIM);   // 32

    round_kernel<<<dim3((unsigned)((size_t)bh * S_LEN * D_DIM / 4 / 256), 2), 256>>>(K, V);

    const size_t smem_bytes = (size_t)SMEM_FLOATS * sizeof(float);
    cudaFuncSetAttribute(attn_mma_kernel, cudaFuncAttributeMaxDynamicSharedMemorySize,
                         (int)smem_bytes);
    attn_mma_kernel<<<dim3(S_LEN / 64, bh), NT, smem_bytes>>>(Q, O);
}

// round 9
// speedup vs baseline: 1.0500x; 1.0500x over previous
#include <cuda_runtime.h>
#include <cstdint>
#include <math.h>

// Shape fixed by setup_inputs: B=2, H=16, S=2048, D=128, key block = 256
#define S_LEN 2048
#define D_DIM 128
#define BH 32
#define NT 512
#define FULLM 0xffffffffu

// smem layout (floats)
#define QSTR 136
#define Q_FLOATS (64 * QSTR)                       // 8704
#define SLOT_FLOATS (64 * 128)                     // 8192 = 32 KB
#define NSLOT 5
#define SLOTS_OFF Q_FLOATS
#define PBUF_OFF (SLOTS_OFF + NSLOT * SLOT_FLOATS)
#define MBAR_OFF (PBUF_OFF + 1024)
#define SMEM_FLOATS (MBAR_OFF + 64)
#define OSTR 132

// Pre-permuted tf32 scratch:
//  g_Kp[bh][key][d_perm]   - pair-interleaved d: group of 8 = [d0,d4,d1,d5,d2,d6,d3,d7]
//  g_Vp[bh][d][key_perm]   - transposed, pair-interleaved keys (same 8-group order)
__device__ float g_Kp[(size_t)BH * S_LEN * D_DIM];
__device__ float g_Vp[(size_t)BH * S_LEN * D_DIM];

__device__ __forceinline__ uint32_t tf32b(float x) {
    uint32_t u; asm("cvt.rna.tf32.f32 %0, %1;" : "=r"(u) : "f"(x)); return u;
}
__device__ __forceinline__ float tf32r(float x) { return __uint_as_float(tf32b(x)); }

__device__ __forceinline__ uint32_t smem_u32(const void* p) {
    uint32_t a;
    asm("{ .reg .u64 t; cvta.to.shared.u64 t, %1; cvt.u32.u64 %0, t; }" : "=r"(a) : "l"(p));
    return a;
}

#define MB_INIT(mb, c) asm volatile("mbarrier.init.shared.b64 [%0], %1;" :: "r"(mb), "r"(c) : "memory")
#define MB_ARRIVE(mb)  asm volatile("mbarrier.arrive.shared.b64 _, [%0];" :: "r"(mb) : "memory")
#define CP16(dst, src) asm volatile("cp.async.cg.shared.global [%0], [%1], 16;" :: "r"(dst), "l"(src) : "memory")
// .noinc is load-bearing (R6 hang without it).
#define CP_ARRIVE(mb)  asm volatile("cp.async.mbarrier.arrive.noinc.shared.b64 [%0];" :: "r"(mb) : "memory")
#define BAR_SYNC(id)   asm volatile("bar.sync %0, 128;" :: "r"(id) : "memory")

#define MB_WAIT(mbar_addr, phase) do {                                             \
    uint32_t _mb = (mbar_addr); uint32_t _ph = (phase); uint32_t _done;            \
    asm volatile("{ .reg .pred p; mbarrier.try_wait.parity.acquire.cta.shared::cta.b64 p, [%1], %2; selp.b32 %0, 1, 0, p; }" \
        : "=r"(_done) : "r"(_mb), "r"(_ph) : "memory");                            \
    if (!_done) {                                                                  \
        asm volatile("{ .reg .pred P1; WL_%=: mbarrier.try_wait.parity.acquire.cta.shared::cta.b64 P1, [%0], %1, 0x989680; @P1 bra.uni WD_%=; bra.uni WL_%=; WD_%=: }" \
            :: "r"(_mb), "r"(_ph) : "memory");                                     \
    }                                                                              \
} while (0)

// m16n8k8 tf32 HMMA, D += A*B
__device__ __forceinline__ void mma8(float* c, uint32_t a0, uint32_t a1,
                                     uint32_t a2, uint32_t a3,
                                     uint32_t b0, uint32_t b1) {
    asm volatile(
        "mma.sync.aligned.m16n8k8.row.col.f32.tf32.tf32.f32 "
        "{%0,%1,%2,%3}, {%4,%5,%6,%7}, {%8,%9}, {%0,%1,%2,%3};"
        : "+f"(c[0]), "+f"(c[1]), "+f"(c[2]), "+f"(c[3])
        : "r"(c[0] == c[0] ? a0 : a0), "r"(a1), "r"(a2), "r"(a3), "r"(b0), "r"(b1));
}

// ---------------------------------------------------------------------------
// Pre-pass 1: K -> g_Kp (tf32 + pair-interleave d within 8-groups)
// Each thread handles one 8-float group.
// ---------------------------------------------------------------------------
__global__ void prep_k_kernel(const float* __restrict__ K) {
    size_t gi = (size_t)blockIdx.x * 256 + threadIdx.x;   // group index
    const float4* s = (const float4*)K;
    float4 lo = s[gi * 2];       // d0..d3
    float4 hi = s[gi * 2 + 1];   // d4..d7
    float4 a = make_float4(tf32r(lo.x), tf32r(hi.x), tf32r(lo.y), tf32r(hi.y));
    float4 b = make_float4(tf32r(lo.z), tf32r(hi.z), tf32r(lo.w), tf32r(hi.w));
    float4* d = (float4*)g_Kp;
    d[gi * 2] = a;
    d[gi * 2 + 1] = b;
}

// ---------------------------------------------------------------------------
// Pre-pass 2: V -> g_Vp (transpose to [d][key], tf32, pair-interleave keys)
// ---------------------------------------------------------------------------
__global__ void prep_v_kernel(const float* __restrict__ V) {
    __shared__ float tile[32][33];
    const int s0 = blockIdx.x * 32;    // key base
    const int d0 = blockIdx.y * 32;    // d base
    const int b  = blockIdx.z;
    const float* Vb = V + (size_t)b * S_LEN * D_DIM;
    float* Vp = g_Vp + (size_t)b * S_LEN * D_DIM;
    const int tx = threadIdx.x;
    #pragma unroll
    for (int i = threadIdx.y; i < 32; i += 8)
        tile[i][tx] = tf32r(Vb[(size_t)(s0 + i) * D_DIM + d0 + tx]);
    __syncthreads();
    // write: row = d, col = permuted key
    const int e = tx & 7;
    const int pc = (tx & ~7) + ((e < 4) ? (2 * e) : (2 * (e - 4) + 1));
    #pragma unroll
    for (int i = threadIdx.y; i < 32; i += 8)
        Vp[(size_t)(d0 + i) * S_LEN + s0 + pc] = tile[tx][i];
}

// ---------------------------------------------------------------------------
// Main kernel. CTA: 64 q rows, 16 warps = 4(m) x 4(kg: 64 keys).
// Ring of 5 32KB slots; K chunks: 64 key-rows x 512B; V chunks: 128 d-rows x 256B.
// 16B-chunk swizzle c' = c ^ 2*(row&7); all fragment loads are LDS.64.
// ---------------------------------------------------------------------------
__global__ __launch_bounds__(NT, 1)
void attn_mma_kernel(const float* __restrict__ Q, float* __restrict__ O) {
    extern __shared__ float smf[];
    const uint32_t sbase = smem_u32(smf);
    const uint32_t slots_sa = sbase + SLOTS_OFF * 4;
    const uint32_t mb_full  = sbase + MBAR_OFF * 4;
    const uint32_t mb_empty = mb_full + NSLOT * 8;
    float* qs = smf;
    float* pmax = smf + PBUF_OFF;
    float* psum = pmax + 512;

    const int tid  = threadIdx.x;
    const int wid  = tid >> 5;
    const int lane = tid & 31;
    const int m  = wid & 3;
    const int kg = wid >> 2;
    const int g = lane >> 2;
    const int t = lane & 3;
    const int thalf = t >> 1;
    const int tlow  = t & 1;
    const int twog  = 2 * g;

    const int bh = blockIdx.y;
    const int qb = blockIdx.x;
    const size_t bhoff = (size_t)bh * S_LEN * D_DIM;
    const float* Qb = Q + bhoff + (size_t)qb * 64 * D_DIM;
    const float* Kpb = g_Kp + bhoff;     // [key][d_perm]
    const float* Vpb = g_Vp + bhoff;     // [d][key_perm]
    float* Ob = O + bhoff + (size_t)qb * 64 * D_DIM;

    if (tid == 0) {
        #pragma unroll
        for (int s = 0; s < NSLOT; s++) {
            MB_INIT(mb_full + s * 8, NT);
            MB_INIT(mb_empty + s * 8, 128);
        }
    }
    __syncthreads();

    // ---- producer: stage chunk n (if n < 64) ----
    auto produce = [&](int n) {
        if (n >= 64) return;
        int q5 = n / 5;
        int slot = n - q5 * 5;
        uint32_t db = slots_sa + (uint32_t)slot * (SLOT_FLOATS * 4);
        if (n >= 5) MB_WAIT(mb_empty + slot * 8, (q5 - 1) & 1);
        int r = n & 7;
        int key_base = (n >> 3) * 256 + (r & 3) * 64;
        if (r < 4) {
            // K chunk: 64 key-rows x 128 d floats (512B rows, 32 chunks)
            const float* src = Kpb + (size_t)key_base * D_DIM;
            #pragma unroll
            for (int i = 0; i < 4; i++) {
                int u = tid + NT * i;           // 0..2047
                int row = u >> 5;               // 0..63
                int c = u & 31;
                int cs = c ^ (2 * (row & 7));
                CP16(db + (uint32_t)row * 512 + (uint32_t)(cs << 4),
                     src + (size_t)row * D_DIM + c * 4);
            }
        } else {
            // V chunk: 128 d-rows x 64 key floats (256B rows, 16 chunks)
            const float* src = Vpb + key_base;
            #pragma unroll
            for (int i = 0; i < 4; i++) {
                int u = tid + NT * i;           // 0..2047
                int row = u >> 4;               // 0..127
                int c = u & 15;
                int cs = c ^ (2 * (row & 7));
                CP16(db + (uint32_t)row * 256 + (uint32_t)(cs << 4),
                     src + (size_t)row * S_LEN + c * 4);
            }
        }
        CP_ARRIVE(mb_full + slot * 8);
    };

    // ---- stage Q (tf32, d pair-interleaved, stride 136) ----
    #pragma unroll
    for (int i = 0; i < 2048 / NT; i++) {
        int idx = tid + NT * i;
        int r = idx >> 5;
        int c4 = (idx & 31) << 2;                     // source d, multiple of 4
        float4 v = *(const float4*)(Qb + (size_t)r * D_DIM + c4);
        // source d c4+j  ->  position (c4&~7) + 2*((c4+j)&3) + ((c4&4)?1:0)
        float* dst = qs + r * QSTR + (c4 & ~7) + ((c4 & 4) ? 1 : 0);
        dst[2 * ((c4 + 0) & 3)] = tf32r(v.x);
        dst[2 * ((c4 + 1) & 3)] = tf32r(v.y);
        dst[2 * ((c4 + 2) & 3)] = tf32r(v.z);
        dst[2 * ((c4 + 3) & 3)] = tf32r(v.w);
    }

    produce(0); produce(1); produce(2); produce(3); produce(4);

    float oacc[16][4];
    #pragma unroll
    for (int dt = 0; dt < 16; dt++)
        #pragma unroll
        for (int j = 0; j < 4; j++) oacc[dt][j] = 0.0f;

    const float cexp = 0.08838834764831845f * 1.4426950408889634f;
    const int srcA = (lane & ~3) | (t >> 1);
    const int srcB = srcA + 2;
    const bool odd = (t & 1) != 0;
    const int row0 = 16 * m + g;
    // A-fragment base: pair (a0,a2) at [row0*QSTR + ks*8 + 2t]
    const float* a0p = qs + row0 * QSTR + 2 * t;
    const float* a1p = a0p + 8 * QSTR;

    __syncthreads();

    #pragma unroll 1
    for (int jb = 0; jb < 8; jb++) {
        const int base = jb * 8;

        // ================= QK consume =================
        const int nk = base + kg;
        const int qk5 = nk / 5, sk = nk - qk5 * 5;
        MB_WAIT(mb_full + sk * 8, qk5 & 1);
        // lane-fixed part of B address: row g, low-half select
        const float* kbl = smf + SLOTS_OFF + sk * SLOT_FLOATS + g * 128 + tlow * 2;

        float c[8][4];
        #pragma unroll
        for (int nt = 0; nt < 8; nt++)
            #pragma unroll
            for (int j = 0; j < 4; j++) c[nt][j] = 0.0f;

        #pragma unroll 4
        for (int ks = 0; ks < 16; ks++) {
            float2 qa = *(const float2*)(a0p + ks * 8);   // (a0, a2) row0
            float2 qb2 = *(const float2*)(a1p + ks * 8);  // (a1, a3) row0+8
            const int cc = (((2 * ks + thalf) ^ twog) << 2);
            #pragma unroll
            for (int nt = 0; nt < 8; nt++) {
                float2 bb = *(const float2*)(kbl + nt * 1024 + cc);
                mma8(c[nt], __float_as_uint(qa.x), __float_as_uint(qb2.x),
                     __float_as_uint(qa.y), __float_as_uint(qb2.y),
                     __float_as_uint(bb.x), __float_as_uint(bb.y));
            }
        }
        MB_ARRIVE(mb_empty + sk * 8);

        produce(base + 5); produce(base + 6); produce(base + 7);

        // ================= softmax (local 64 keys) ============================
        float m0 = -INFINITY, m1 = -INFINITY;
        #pragma unroll
        for (int nt = 0; nt < 8; nt++) {
            m0 = fmaxf(m0, fmaxf(c[nt][0], c[nt][1]));
            m1 = fmaxf(m1, fmaxf(c[nt][2], c[nt][3]));
        }
        m0 = fmaxf(m0, __shfl_xor_sync(FULLM, m0, 1));
        m0 = fmaxf(m0, __shfl_xor_sync(FULLM, m0, 2));
        m1 = fmaxf(m1, __shfl_xor_sync(FULLM, m1, 1));
        m1 = fmaxf(m1, __shfl_xor_sync(FULLM, m1, 2));

        float s0 = 0.0f, s1 = 0.0f;
        #pragma unroll
        for (int nt = 0; nt < 8; nt++) {
            c[nt][0] = exp2f((c[nt][0] - m0) * cexp); s0 += c[nt][0];
            c[nt][1] = exp2f((c[nt][1] - m0) * cexp); s0 += c[nt][1];
            c[nt][2] = exp2f((c[nt][2] - m1) * cexp); s1 += c[nt][2];
            c[nt][3] = exp2f((c[nt][3] - m1) * cexp); s1 += c[nt][3];
        }
        s0 += __shfl_xor_sync(FULLM, s0, 1);
        s0 += __shfl_xor_sync(FULLM, s0, 2);
        s1 += __shfl_xor_sync(FULLM, s1, 1);
        s1 += __shfl_xor_sync(FULLM, s1, 2);

        float* pmx = pmax + (jb & 1) * 256;
        float* psm = psum + (jb & 1) * 256;
        if (t == 0) {
            pmx[kg * 64 + row0] = m0;  pmx[kg * 64 + row0 + 8] = m1;
            psm[kg * 64 + row0] = s0;  psm[kg * 64 + row0 + 8] = s1;
        }
        BAR_SYNC(1 + m);   // merge scope = this m-group's 4 warps

        float scale0, scale1;
        {
            float M0 = -INFINITY, M1 = -INFINITY;
            #pragma unroll
            for (int j = 0; j < 4; j++) {
                M0 = fmaxf(M0, pmx[j * 64 + row0]);
                M1 = fmaxf(M1, pmx[j * 64 + row0 + 8]);
            }
            float S0 = 0.0f, S1 = 0.0f;
            #pragma unroll
            for (int j = 0; j < 4; j++) {
                S0 += psm[j * 64 + row0]     * exp2f((pmx[j * 64 + row0]     - M0) * cexp);
                S1 += psm[j * 64 + row0 + 8] * exp2f((pmx[j * 64 + row0 + 8] - M1) * cexp);
            }
            scale0 = exp2f((m0 - M0) * cexp) / S0;
            scale1 = exp2f((m1 - M1) * cexp) / S1;
        }

        produce(base + 8);

        // ===== permute P: C-layout -> A-layout, tf32 ========
        #pragma unroll
        for (int nt = 0; nt < 8; nt++) {
            float x0 = c[nt][0] * scale0, x1 = c[nt][1] * scale0;
            float x2 = c[nt][2] * scale1, x3 = c[nt][3] * scale1;
            float e0 = __shfl_sync(FULLM, x0, srcA), e1 = __shfl_sync(FULLM, x1, srcA);
            float f0 = __shfl_sync(FULLM, x0, srcB), f1 = __shfl_sync(FULLM, x1, srcB);
            float u0 = __shfl_sync(FULLM, x2, srcA), u1 = __shfl_sync(FULLM, x3, srcA);
            float v0 = __shfl_sync(FULLM, x2, srcB), v1 = __shfl_sync(FULLM, x3, srcB);
            c[nt][0] = tf32r(odd ? e1 : e0);
            c[nt][1] = tf32r(odd ? u1 : u0);
            c[nt][2] = tf32r(odd ? f1 : f0);
            c[nt][3] = tf32r(odd ? v1 : v0);
        }

        // ================= PV consume =================
        const int nv = base + 4 + kg;
        const int qv5 = nv / 5, sv = nv - qv5 * 5;
        MB_WAIT(mb_full + sv * 8, qv5 & 1);
        const float* vbl = smf + SLOTS_OFF + sv * SLOT_FLOATS + g * 64 + tlow * 2;

        #pragma unroll 2
        for (int kc = 0; kc < 8; kc++) {
            const int cc = (((2 * kc + thalf) ^ twog) << 2);
            uint32_t A0 = __float_as_uint(c[kc][0]);
            uint32_t A1 = __float_as_uint(c[kc][1]);
            uint32_t A2 = __float_as_uint(c[kc][2]);
            uint32_t A3 = __float_as_uint(c[kc][3]);
            #pragma unroll
            for (int dt = 0; dt < 16; dt++) {
                float2 bb = *(const float2*)(vbl + dt * 512 + cc);
                mma8(oacc[dt], A0, A1, A2, A3,
                     __float_as_uint(bb.x), __float_as_uint(bb.y));
            }
        }
        MB_ARRIVE(mb_empty + sv * 8);

        produce(base + 9); produce(base + 10); produce(base + 11); produce(base + 12);
    }

    // ================= combine 4 kg partials, write O =========================
    __syncthreads();
    float* obuf = smf;
    if (kg != 0) {
        float* p0 = obuf + ((kg - 1) * 64 + row0) * OSTR + 2 * t;
        float* p1 = p0 + 8 * OSTR;
        #pragma unroll
        for (int dt = 0; dt < 16; dt++) {
            *(float2*)(p0 + dt * 8) = make_float2(oacc[dt][0], oacc[dt][1]);
            *(float2*)(p1 + dt * 8) = make_float2(oacc[dt][2], oacc[dt][3]);
        }
    }
    __syncthreads();
    if (kg == 0) {
        float* o0 = Ob + (size_t)row0 * D_DIM + 2 * t;
        float* o1 = o0 + 8 * D_DIM;
        const float* p0 = obuf + row0 * OSTR + 2 * t;
        const float* p1 = p0 + 8 * OSTR;
        #pragma unroll
        for (int dt = 0; dt < 16; dt++) {
            float a0 = oacc[dt][0], a1 = oacc[dt][1];
            float a2 = oacc[dt][2], a3 = oacc[dt][3];
            #pragma unroll
            for (int j = 0; j < 3; j++) {
                float2 q0 = *(const float2*)(p0 + j * 64 * OSTR + dt * 8);
                float2 q1 = *(const float2*)(p1 + j * 64 * OSTR + dt * 8);
                a0 += q0.x; a1 += q0.y; a2 += q1.x; a3 += q1.y;
            }
            *(float2*)(o0 + dt * 8) = make_float2(a0, a1);
            *(float2*)(o1 + dt * 8) = make_float2(a2, a3);
        }
    }
}

// ---------------------------------------------------------------------------
extern "C" void kernel_launch(void* const* d_in, const int* in_sizes, int n_in,
                              void* d_out, int out_size) {
    const float* Q = (const float*)d_in[0];
    const float* K = (const float*)d_in[1];
    const float* V = (const float*)d_in[2];
    float* O = (float*)d_out;

    const int bh = in_sizes[0] / (S_LEN * D_DIM);   // 32

    prep_k_kernel<<<(unsigned)((size_t)bh * S_LEN * D_DIM / 8 / 256), 256>>>(K);
    prep_v_kernel<<<dim3(S_LEN / 32, D_DIM / 32, bh), dim3(32, 8)>>>(V);

    const size_t smem_bytes = (size_t)SMEM_FLOATS * sizeof(float);
    cudaFuncSetAttribute(attn_mma_kernel, cudaFuncAttributeMaxDynamicSharedMemorySize,
                         (int)smem_bytes);
    attn_mma_kernel<<<dim3(S_LEN / 64, bh), NT, smem_bytes>>>(Q, O);
}

// round 10
// speedup vs baseline: 2.1669x; 2.0638x over previous
#include <cuda_runtime.h>
#include <cuda_fp16.h>
#include <cstdint>
#include <math.h>

// Shape fixed by setup_inputs: B=2, H=16, S=2048, D=128, key block = 256
#define S_LEN 2048
#define D_DIM 128
#define BH 32
#define NT 512
#define FULLM 0xffffffffu

// smem layout (bytes)
#define Q_BYTES   (64 * 288)                 // 18432 (fp16, stride 288B/row)
#define SLOT_B    16384                      // 16 KB per chunk slot
#define NSLOT     8
#define SLOTS_OFF Q_BYTES
#define PBUF_OFF  (SLOTS_OFF + NSLOT * SLOT_B)   // 149504: pmax[2][256]+psum[2][256] f32
#define MBAR_OFF  (PBUF_OFF + 4096)              // 153600: 16 x u64
#define SMEM_BYTES (MBAR_OFF + 128)              // 153728
#define OSTR 132

// fp16 scratch, 16B-aligned:
//  g_Kh[bh][key][d interleaved in 16-groups: d0,d1,d8,d9,d2,d3,d10,d11,...]
//  g_Vh[bh][d][key interleaved same way]
__device__ uint4 g_Kh[(size_t)BH * S_LEN * D_DIM / 8];
__device__ uint4 g_Vh[(size_t)BH * S_LEN * D_DIM / 8];

__device__ __forceinline__ uint32_t f16x2(float hi, float lo) {
    uint32_t d; asm("cvt.rn.f16x2.f32 %0, %1, %2;" : "=r"(d) : "f"(hi), "f"(lo));
    return d;
}
__device__ __forceinline__ uint32_t smem_u32(const void* p) {
    uint32_t a;
    asm("{ .reg .u64 t; cvta.to.shared.u64 t, %1; cvt.u32.u64 %0, t; }" : "=r"(a) : "l"(p));
    return a;
}

#define MB_INIT(mb, c) asm volatile("mbarrier.init.shared.b64 [%0], %1;" :: "r"(mb), "r"(c) : "memory")
#define MB_ARRIVE(mb)  asm volatile("mbarrier.arrive.shared.b64 _, [%0];" :: "r"(mb) : "memory")
#define CP16(dst, src) asm volatile("cp.async.cg.shared.global [%0], [%1], 16;" :: "r"(dst), "l"(src) : "memory")
// .noinc is load-bearing (R6 hang without it).
#define CP_ARRIVE(mb)  asm volatile("cp.async.mbarrier.arrive.noinc.shared.b64 [%0];" :: "r"(mb) : "memory")
#define BAR_SYNC(id)   asm volatile("bar.sync %0, 128;" :: "r"(id) : "memory")

#define MB_WAIT(mbar_addr, phase) do {                                             \
    uint32_t _mb = (mbar_addr); uint32_t _ph = (phase); uint32_t _done;            \
    asm volatile("{ .reg .pred p; mbarrier.try_wait.parity.acquire.cta.shared::cta.b64 p, [%1], %2; selp.b32 %0, 1, 0, p; }" \
        : "=r"(_done) : "r"(_mb), "r"(_ph) : "memory");                            \
    if (!_done) {                                                                  \
        asm volatile("{ .reg .pred P1; WL_%=: mbarrier.try_wait.parity.acquire.cta.shared::cta.b64 P1, [%0], %1, 0x989680; @P1 bra.uni WD_%=; bra.uni WL_%=; WD_%=: }" \
            :: "r"(_mb), "r"(_ph) : "memory");                                     \
    }                                                                              \
} while (0)

// m16n8k16 fp16 HMMA, D(f32) += A(f16)*B(f16)
__device__ __forceinline__ void mma16(float* c, uint32_t a0, uint32_t a1,
                                      uint32_t a2, uint32_t a3,
                                      uint32_t b0, uint32_t b1) {
    asm volatile(
        "mma.sync.aligned.m16n8k16.row.col.f32.f16.f16.f32 "
        "{%0,%1,%2,%3}, {%4,%5,%6,%7}, {%8,%9}, {%0,%1,%2,%3};"
        : "+f"(c[0]), "+f"(c[1]), "+f"(c[2]), "+f"(c[3])
        : "r"(a0), "r"(a1), "r"(a2), "r"(a3), "r"(b0), "r"(b1));
}

// ---------------------------------------------------------------------------
// Pre-pass 1: K fp32 [key][d] -> g_Kh fp16, d pair-interleaved per 16-group.
// One thread per 16-d group.
// ---------------------------------------------------------------------------
__global__ void prep_k_kernel(const float* __restrict__ K) {
    size_t gi = (size_t)blockIdx.x * 256 + threadIdx.x;
    const float4* s = (const float4*)K;
    float4 v0 = s[gi * 4 + 0], v1 = s[gi * 4 + 1];
    float4 v2 = s[gi * 4 + 2], v3 = s[gi * 4 + 3];
    uint4 o0, o1;
    o0.x = f16x2(v0.y, v0.x);   // (d0,d1)
    o0.y = f16x2(v2.y, v2.x);   // (d8,d9)
    o0.z = f16x2(v0.w, v0.z);   // (d2,d3)
    o0.w = f16x2(v2.w, v2.z);   // (d10,d11)
    o1.x = f16x2(v1.y, v1.x);   // (d4,d5)
    o1.y = f16x2(v3.y, v3.x);   // (d12,d13)
    o1.z = f16x2(v1.w, v1.z);   // (d6,d7)
    o1.w = f16x2(v3.w, v3.z);   // (d14,d15)
    g_Kh[gi * 2] = o0;
    g_Kh[gi * 2 + 1] = o1;
}

// ---------------------------------------------------------------------------
// Pre-pass 2: V fp32 [key][d] -> g_Vh fp16 [d][key interleaved per 16-group].
// ---------------------------------------------------------------------------
__global__ void prep_v_kernel(const float* __restrict__ V) {
    __shared__ float tile[32][33];
    const int s0 = blockIdx.x * 32;    // key base
    const int d0 = blockIdx.y * 32;    // d base
    const int b  = blockIdx.z;
    const float* Vb = V + (size_t)b * S_LEN * D_DIM;
    __half* Vh = (__half*)g_Vh + (size_t)b * S_LEN * D_DIM;
    const int tx = threadIdx.x;
    #pragma unroll
    for (int i = threadIdx.y; i < 32; i += 8)
        tile[i][tx] = Vb[(size_t)(s0 + i) * D_DIM + d0 + tx];
    __syncthreads();
    const int e = tx & 15;
    const int pos = (e < 8) ? (4 * (e >> 1) + (e & 1))
                            : (4 * ((e - 8) >> 1) + 2 + (e & 1));
    const int pc = (tx & 16) + pos;
    #pragma unroll
    for (int i = threadIdx.y; i < 32; i += 8)
        Vh[(size_t)(d0 + i) * S_LEN + s0 + pc] = __float2half_rn(tile[tx][i]);
}

// ---------------------------------------------------------------------------
// Main kernel. CTA: 64 q rows, 16 warps = 4(m) x 4(kg: 64 keys), fp16 HMMA.
// 8-slot ring of 16KB chunks (slot = chunk&7, phase = chunk>>3 parity).
// K slot: 64 rows x 256B, swizzle c^=2*(row&7). V slot: 128 rows x 128B,
// swizzle c^=2*(row&3). All fragment loads LDS.64; P->A is scale+cvt only.
// ---------------------------------------------------------------------------
__global__ __launch_bounds__(NT, 1)
void attn_mma_kernel(const float* __restrict__ Q, float* __restrict__ O) {
    extern __shared__ char smc[];
    const uint32_t sbase = smem_u32(smc);
    const uint32_t slots_sa = sbase + SLOTS_OFF;
    const uint32_t mb_full  = sbase + MBAR_OFF;
    const uint32_t mb_empty = mb_full + NSLOT * 8;
    float* pmax = (float*)(smc + PBUF_OFF);       // [2][256]
    float* psum = pmax + 512;

    const int tid  = threadIdx.x;
    const int wid  = tid >> 5;
    const int lane = tid & 31;
    const int m  = wid & 3;
    const int kg = wid >> 2;
    const int g = lane >> 2;
    const int t = lane & 3;
    const int thalf = t >> 1;
    const int tb8   = 8 * (t & 1);     // byte offset within 16B chunk

    const int bh = blockIdx.y;
    const int qb = blockIdx.x;
    const size_t bhoff = (size_t)bh * S_LEN * D_DIM;
    const float* Qb = Q + bhoff + (size_t)qb * 64 * D_DIM;
    const __half* Khb = (const __half*)g_Kh + bhoff;
    const __half* Vhb = (const __half*)g_Vh + bhoff;
    float* Ob = O + bhoff + (size_t)qb * 64 * D_DIM;

    if (tid == 0) {
        #pragma unroll
        for (int s = 0; s < NSLOT; s++) {
            MB_INIT(mb_full + s * 8, NT);
            MB_INIT(mb_empty + s * 8, 128);
        }
    }
    __syncthreads();

    // ---- producer: stage 16KB chunk n (if n < 64) ----
    auto produce = [&](int n) {
        if (n >= 64) return;
        int slot = n & 7;
        uint32_t db = slots_sa + (uint32_t)slot * SLOT_B;
        if (n >= 8) MB_WAIT(mb_empty + slot * 8, ((n >> 3) + 1) & 1);
        int key_base = (n >> 3) * 256 + (n & 3) * 64;
        if ((n & 7) < 4) {
            // K chunk: 64 key rows x 256B
            const __half* src = Khb + (size_t)key_base * D_DIM;
            #pragma unroll
            for (int i = 0; i < 2; i++) {
                int u = tid + NT * i;          // 0..1023
                int row = u >> 4, c = u & 15;
                int cs = c ^ (2 * (row & 7));
                CP16(db + (uint32_t)(row * 256 + cs * 16),
                     src + row * D_DIM + c * 8);
            }
        } else {
            // V chunk: 128 d rows x 128B
            const __half* src = Vhb + key_base;
            #pragma unroll
            for (int i = 0; i < 2; i++) {
                int u = tid + NT * i;
                int row = u >> 3, c = u & 7;
                int cs = c ^ (2 * (row & 3));
                CP16(db + (uint32_t)(row * 128 + cs * 16),
                     src + (size_t)row * S_LEN + c * 8);
            }
        }
        CP_ARRIVE(mb_full + slot * 8);
    };

    // ---- stage Q: fp16, d pair-interleaved, 288B row stride ----
    #pragma unroll
    for (int i = 0; i < 4; i++) {
        int idx = tid + NT * i;                  // 0..2047
        int r = idx >> 5;
        int c4 = (idx & 31) << 2;
        float4 v = *(const float4*)(Qb + (size_t)r * D_DIM + c4);
        int q4 = (c4 >> 2) & 3;
        int w1 = ((q4 & 1) << 2) | (q4 >> 1);
        uint32_t* dst = (uint32_t*)(smc + r * 288 + (c4 >> 4) * 32);
        dst[w1]     = f16x2(v.y, v.x);
        dst[w1 + 2] = f16x2(v.w, v.z);
    }

    produce(0); produce(1); produce(2); produce(3); produce(4);

    float oacc[16][4];
    #pragma unroll
    for (int dt = 0; dt < 16; dt++)
        #pragma unroll
        for (int j = 0; j < 4; j++) oacc[dt][j] = 0.0f;

    const float cexp = 0.08838834764831845f * 1.4426950408889634f;
    const int row0 = 16 * m + g;
    // A pairs: (a0,a2) at row0, (a1,a3) at row0+8; byte = ks*32 + 8t
    const char* a0p = smc + row0 * 288 + 8 * t;
    const char* a1p = a0p + 8 * 288;

    __syncthreads();

    #pragma unroll 1
    for (int jb = 0; jb < 8; jb++) {
        const int base = jb * 8;
        const int ph = jb & 1;

        // ================= QK consume: chunk base+kg (slot kg) ================
        MB_WAIT(mb_full + kg * 8, ph);
        const char* kbl = smc + SLOTS_OFF + kg * SLOT_B + g * 256 + tb8;

        float c[8][4];
        #pragma unroll
        for (int nt = 0; nt < 8; nt++)
            #pragma unroll
            for (int j = 0; j < 4; j++) c[nt][j] = 0.0f;

        #pragma unroll 2
        for (int ks = 0; ks < 8; ks++) {
            uint2 qa = *(const uint2*)(a0p + ks * 32);   // (a0, a2)
            uint2 qb2 = *(const uint2*)(a1p + ks * 32);  // (a1, a3)
            const int cc = ((2 * ks + thalf) ^ (2 * g)) << 4;
            #pragma unroll
            for (int nt = 0; nt < 8; nt++) {
                uint2 bb = *(const uint2*)(kbl + nt * 2048 + cc);
                mma16(c[nt], qa.x, qb2.x, qa.y, qb2.y, bb.x, bb.y);
            }
        }
        MB_ARRIVE(mb_empty + kg * 8);

        produce(base + 5); produce(base + 6); produce(base + 7);

        // ================= softmax (local 64 keys) ============================
        float m0 = -INFINITY, m1 = -INFINITY;
        #pragma unroll
        for (int nt = 0; nt < 8; nt++) {
            m0 = fmaxf(m0, fmaxf(c[nt][0], c[nt][1]));
            m1 = fmaxf(m1, fmaxf(c[nt][2], c[nt][3]));
        }
        m0 = fmaxf(m0, __shfl_xor_sync(FULLM, m0, 1));
        m0 = fmaxf(m0, __shfl_xor_sync(FULLM, m0, 2));
        m1 = fmaxf(m1, __shfl_xor_sync(FULLM, m1, 1));
        m1 = fmaxf(m1, __shfl_xor_sync(FULLM, m1, 2));

        float s0 = 0.0f, s1 = 0.0f;
        #pragma unroll
        for (int nt = 0; nt < 8; nt++) {
            c[nt][0] = exp2f((c[nt][0] - m0) * cexp); s0 += c[nt][0];
            c[nt][1] = exp2f((c[nt][1] - m0) * cexp); s0 += c[nt][1];
            c[nt][2] = exp2f((c[nt][2] - m1) * cexp); s1 += c[nt][2];
            c[nt][3] = exp2f((c[nt][3] - m1) * cexp); s1 += c[nt][3];
        }
        s0 += __shfl_xor_sync(FULLM, s0, 1);
        s0 += __shfl_xor_sync(FULLM, s0, 2);
        s1 += __shfl_xor_sync(FULLM, s1, 1);
        s1 += __shfl_xor_sync(FULLM, s1, 2);

        float* pmx = pmax + ph * 256;
        float* psm = psum + ph * 256;
        if (t == 0) {
            pmx[kg * 64 + row0] = m0;  pmx[kg * 64 + row0 + 8] = m1;
            psm[kg * 64 + row0] = s0;  psm[kg * 64 + row0 + 8] = s1;
        }
        BAR_SYNC(1 + m);   // merge scope = this m-group's 4 warps

        float scale0, scale1;
        {
            float M0 = -INFINITY, M1 = -INFINITY;
            #pragma unroll
            for (int j = 0; j < 4; j++) {
                M0 = fmaxf(M0, pmx[j * 64 + row0]);
                M1 = fmaxf(M1, pmx[j * 64 + row0 + 8]);
            }
            float S0 = 0.0f, S1 = 0.0f;
            #pragma unroll
            for (int j = 0; j < 4; j++) {
                S0 += psm[j * 64 + row0]     * exp2f((pmx[j * 64 + row0]     - M0) * cexp);
                S1 += psm[j * 64 + row0 + 8] * exp2f((pmx[j * 64 + row0 + 8] - M1) * cexp);
            }
            scale0 = exp2f((m0 - M0) * cexp) / S0;
            scale1 = exp2f((m1 - M1) * cexp) / S1;
        }

        produce(base + 8);

        // ===== P -> fp16 A fragments: scale + pack (no shuffles needed) =======
        uint32_t pA[4][4];
        #pragma unroll
        for (int kc = 0; kc < 4; kc++) {
            pA[kc][0] = f16x2(c[2 * kc][1] * scale0,     c[2 * kc][0] * scale0);
            pA[kc][1] = f16x2(c[2 * kc][3] * scale1,     c[2 * kc][2] * scale1);
            pA[kc][2] = f16x2(c[2 * kc + 1][1] * scale0, c[2 * kc + 1][0] * scale0);
            pA[kc][3] = f16x2(c[2 * kc + 1][3] * scale1, c[2 * kc + 1][2] * scale1);
        }

        // ================= PV consume: chunk base+4+kg (slot 4+kg) ============
        MB_WAIT(mb_full + (4 + kg) * 8, ph);
        const char* vbl = smc + SLOTS_OFF + (4 + kg) * SLOT_B + g * 128 + tb8;

        #pragma unroll 2
        for (int kc = 0; kc < 4; kc++) {
            const int cc = ((2 * kc + thalf) ^ (2 * (g & 3))) << 4;
            #pragma unroll
            for (int dt = 0; dt < 16; dt++) {
                uint2 bb = *(const uint2*)(vbl + dt * 1024 + cc);
                mma16(oacc[dt], pA[kc][0], pA[kc][1], pA[kc][2], pA[kc][3],
                      bb.x, bb.y);
            }
        }
        MB_ARRIVE(mb_empty + (4 + kg) * 8);

        produce(base + 9); produce(base + 10); produce(base + 11); produce(base + 12);
    }

    // ================= combine 4 kg partials, write O =========================
    __syncthreads();
    float* obuf = (float*)smc;
    if (kg != 0) {
        float* p0 = obuf + ((kg - 1) * 64 + row0) * OSTR + 2 * t;
        float* p1 = p0 + 8 * OSTR;
        #pragma unroll
        for (int dt = 0; dt < 16; dt++) {
            *(float2*)(p0 + dt * 8) = make_float2(oacc[dt][0], oacc[dt][1]);
            *(float2*)(p1 + dt * 8) = make_float2(oacc[dt][2], oacc[dt][3]);
        }
    }
    __syncthreads();
    if (kg == 0) {
        float* o0 = Ob + (size_t)row0 * D_DIM + 2 * t;
        float* o1 = o0 + 8 * D_DIM;
        const float* p0 = obuf + row0 * OSTR + 2 * t;
        const float* p1 = p0 + 8 * OSTR;
        #pragma unroll
        for (int dt = 0; dt < 16; dt++) {
            float a0 = oacc[dt][0], a1 = oacc[dt][1];
            float a2 = oacc[dt][2], a3 = oacc[dt][3];
            #pragma unroll
            for (int j = 0; j < 3; j++) {
                float2 q0 = *(const float2*)(p0 + j * 64 * OSTR + dt * 8);
                float2 q1 = *(const float2*)(p1 + j * 64 * OSTR + dt * 8);
                a0 += q0.x; a1 += q0.y; a2 += q1.x; a3 += q1.y;
            }
            *(float2*)(o0 + dt * 8) = make_float2(a0, a1);
            *(float2*)(o1 + dt * 8) = make_float2(a2, a3);
        }
    }
}

// ---------------------------------------------------------------------------
extern "C" void kernel_launch(void* const* d_in, const int* in_sizes, int n_in,
                              void* d_out, int out_size) {
    const float* Q = (const float*)d_in[0];
    const float* K = (const float*)d_in[1];
    const float* V = (const float*)d_in[2];
    float* O = (float*)d_out;

    const int bh = in_sizes[0] / (S_LEN * D_DIM);   // 32

    prep_k_kernel<<<(unsigned)((size_t)bh * S_LEN * D_DIM / 16 / 256), 256>>>(K);
    prep_v_kernel<<<dim3(S_LEN / 32, D_DIM / 32, bh), dim3(32, 8)>>>(V);

    cudaFuncSetAttribute(attn_mma_kernel, cudaFuncAttributeMaxDynamicSharedMemorySize,
                         SMEM_BYTES);
    attn_mma_kernel<<<dim3(S_LEN / 64, bh), NT, SMEM_BYTES>>>(Q, O);
}